// round 1
// baseline (speedup 1.0000x reference)
#include <cuda_runtime.h>
#include <math.h>

// ---------------------------------------------------------------------------
// FourierBlock: rfft(L=4096) -> top-16 |X| per (b,c) -> mask -> irfft
// x: [B=64, L=4096, C=128] f32
//
// Pipeline:
//   k0: twiddle init (double-precision sincos -> f32 table)
//   k1: transpose [B,L,C] -> scratch [B,C,L]       (coalesced both sides)
//   k2: per-series kernel (1 CTA per (b,c)):
//        packed real FFT (complex 2048, Stockham radix 8,8,8,4, smem ping-pong)
//        untangle -> magnitudes -> iterative top-16 argmax
//        masked spectrum -> inverse untangle -> inverse FFT (conj trick)
//        write back in place into scratch
//   k3: transpose scratch [B,C,L] -> out [B,L,C]
// ---------------------------------------------------------------------------

#define BATCH 64
#define LEN   4096
#define CH    128
#define NC    2048            // complex FFT size
#define NF    2049            // rfft bins
#define TPB   256

// padded smem mapping to reduce bank conflicts on strided butterfly writes
#define MAP(i) ((i) + ((i) >> 4))
#define BUFSZ  (MAP(2048) + 8)   // max index MAP(2048)=2176

__device__ float  g_scratch[BATCH * CH * LEN];   // 134 MB scratch
__device__ float2 g_tw[NC];                      // W_2048^k = cis(-2*pi*k/2048)

// ------------------------------ complex helpers ----------------------------
__device__ __forceinline__ float2 cmul(float2 a, float2 b) {
    return make_float2(fmaf(a.x, b.x, -a.y * b.y), fmaf(a.x, b.y, a.y * b.x));
}
__device__ __forceinline__ float2 cadd(float2 a, float2 b) {
    return make_float2(a.x + b.x, a.y + b.y);
}
__device__ __forceinline__ float2 csub(float2 a, float2 b) {
    return make_float2(a.x - b.x, a.y - b.y);
}

__device__ __forceinline__ void dft4(float2 v[4]) {
    float2 t0 = cadd(v[0], v[2]);
    float2 t1 = csub(v[0], v[2]);
    float2 t2 = cadd(v[1], v[3]);
    float2 t3 = csub(v[1], v[3]);
    v[0] = cadd(t0, t2);
    v[2] = csub(t0, t2);
    v[1] = make_float2(t1.x + t3.y, t1.y - t3.x);   // t1 - i*t3
    v[3] = make_float2(t1.x - t3.y, t1.y + t3.x);   // t1 + i*t3
}

__device__ __forceinline__ void dft8(float2 v[8]) {
    float2 e[4] = { v[0], v[2], v[4], v[6] };
    float2 o[4] = { v[1], v[3], v[5], v[7] };
    dft4(e);
    dft4(o);
    const float s = 0.70710678118654752f;
    // o1 *= s*(1-i); o2 *= -i; o3 *= s*(-1-i)
    o[1] = make_float2(s * (o[1].x + o[1].y), s * (o[1].y - o[1].x));
    o[2] = make_float2(o[2].y, -o[2].x);
    o[3] = make_float2(s * (o[3].y - o[3].x), -s * (o[3].x + o[3].y));
#pragma unroll
    for (int k = 0; k < 4; k++) {
        v[k]     = cadd(e[k], o[k]);
        v[k + 4] = csub(e[k], o[k]);
    }
}

// ------------------------------ Stockham passes ----------------------------
// read stride N/R, twiddle cis(-2*pi*r*(j%Ns)/(Ns*R)) = g_tw[r * (j%Ns) * (2048/(Ns*R))]
template <int NS>
__device__ __forceinline__ void pass8(const float2* __restrict__ src,
                                      float2* __restrict__ dst, int j) {
    float2 v[8];
#pragma unroll
    for (int r = 0; r < 8; r++) v[r] = src[MAP(j + r * 256)];
    if (NS > 1) {
        int k0 = (j & (NS - 1)) * (256 / NS);
#pragma unroll
        for (int r = 1; r < 8; r++) v[r] = cmul(v[r], __ldg(&g_tw[k0 * r]));
    }
    dft8(v);
    int idxD = ((j & ~(NS - 1)) << 3) + (j & (NS - 1)); // (j/NS)*NS*8 + j%NS
#pragma unroll
    for (int r = 0; r < 8; r++) dst[MAP(idxD + r * NS)] = v[r];
}

// final radix-4 pass, Ns=512: idxD == jj, twiddle step 1
__device__ __forceinline__ void pass4_512(const float2* __restrict__ src,
                                          float2* __restrict__ dst, int jj) {
    float2 v[4];
#pragma unroll
    for (int r = 0; r < 4; r++) v[r] = src[MAP(jj + r * 512)];
#pragma unroll
    for (int r = 1; r < 4; r++) v[r] = cmul(v[r], __ldg(&g_tw[jj * r]));
    dft4(v);
#pragma unroll
    for (int r = 0; r < 4; r++) dst[MAP(jj + r * 512)] = v[r];
}

// forward complex FFT of 2048, data starts in A, ends in A (natural order)
__device__ __forceinline__ void fft2048(float2* A, float2* B, int tid) {
    pass8<1>(A, B, tid);
    __syncthreads();
    pass8<8>(B, A, tid);
    __syncthreads();
    pass8<64>(A, B, tid);
    __syncthreads();
    pass4_512(B, A, tid);
    pass4_512(B, A, tid + 256);
    __syncthreads();
}

// ------------------------------ main FFT kernel ----------------------------
__global__ void __launch_bounds__(TPB) fourier_block_kernel() {
    __shared__ float2 bufA[BUFSZ];
    __shared__ float2 bufB[BUFSZ];
    __shared__ float  mag[NF];
    __shared__ int    keep[16];
    __shared__ float  rv[8];
    __shared__ int    ri[8];

    const int tid = threadIdx.x;
    const size_t ser = blockIdx.x;                 // b*128 + c
    float2* series = reinterpret_cast<float2*>(g_scratch) + ser * NC;

    // load packed real series: z[n] = x[2n] + i*x[2n+1]
    for (int n = tid; n < NC; n += TPB) bufA[MAP(n)] = series[n];
    __syncthreads();

    fft2048(bufA, bufB, tid);                      // Z in bufA

    // untangle -> magnitudes
    const float PIC = 3.14159265358979323846f * (1.0f / 2048.0f);
    for (int f = tid; f < NF; f += TPB) {
        float2 Zf = bufA[MAP(f & (NC - 1))];
        float2 Zn = bufA[MAP((NC - f) & (NC - 1))];
        float2 S  = make_float2(Zf.x + Zn.x, Zf.y - Zn.y);   // Zf + conj(Zn)
        float2 D  = make_float2(Zf.x - Zn.x, Zf.y + Zn.y);   // Zf - conj(Zn)
        float sn, cs;
        __sincosf(0.0f, &sn, &cs); // (placeholder ensures no dead-code warning)
        sincosf(PIC * (float)f, &sn, &cs);
        // X = 0.5*(S - i*W*D), W = cis(-theta) -> i*W = (sn, cs)
        float2 T = cmul(make_float2(sn, cs), D);
        float2 X = make_float2(0.5f * (S.x - T.x), 0.5f * (S.y - T.y));
        mag[f] = sqrtf(X.x * X.x + X.y * X.y);
    }
    __syncthreads();

    // iterative top-16 argmax (stable: equal values -> smaller index first)
    for (int it = 0; it < 16; it++) {
        float best = -1.0f;
        int   bi   = 1 << 20;
        for (int f = tid; f < NF; f += TPB) {
            float v = mag[f];
            if (v > best) { best = v; bi = f; }
        }
#pragma unroll
        for (int o = 16; o; o >>= 1) {
            float ov = __shfl_down_sync(0xffffffffu, best, o);
            int   oi = __shfl_down_sync(0xffffffffu, bi, o);
            if (ov > best || (ov == best && oi < bi)) { best = ov; bi = oi; }
        }
        if ((tid & 31) == 0) { rv[tid >> 5] = best; ri[tid >> 5] = bi; }
        __syncthreads();
        if (tid == 0) {
            float b2 = -2.0f;
            int   i2 = 1 << 20;
#pragma unroll
            for (int w = 0; w < 8; w++) {
                if (rv[w] > b2 || (rv[w] == b2 && ri[w] < i2)) { b2 = rv[w]; i2 = ri[w]; }
            }
            keep[it] = i2;
            mag[i2]  = -1.0f;
        }
        __syncthreads();
    }

    // masked spectrum X' into bufB (recompute untangle; bufA still holds Z)
    for (int f = tid; f < NF; f += TPB) {
        float2 Zf = bufA[MAP(f & (NC - 1))];
        float2 Zn = bufA[MAP((NC - f) & (NC - 1))];
        float2 S  = make_float2(Zf.x + Zn.x, Zf.y - Zn.y);
        float2 D  = make_float2(Zf.x - Zn.x, Zf.y + Zn.y);
        float sn, cs;
        sincosf(PIC * (float)f, &sn, &cs);
        float2 T = cmul(make_float2(sn, cs), D);
        float2 X = make_float2(0.5f * (S.x - T.x), 0.5f * (S.y - T.y));
        bool kf = false;
#pragma unroll
        for (int i = 0; i < 16; i++) kf |= (keep[i] == f);
        bufB[MAP(f)] = kf ? X : make_float2(0.0f, 0.0f);
    }
    __syncthreads();

    // inverse untangle: Z'[g] from X'[g], X'[2048-g]; store conj(Z') for conj-trick
    for (int g = tid; g < NC; g += TPB) {
        float2 Xg = bufB[MAP(g)];
        float2 Xn = bufB[MAP(NC - g)];
        float2 S  = make_float2(Xg.x + Xn.x, Xg.y - Xn.y);        // Xg + conj(Xn)
        float2 Q  = make_float2(Xn.x - Xg.x, -Xn.y - Xg.y);       // conj(Xn) - Xg
        float sn, cs;
        sincosf(PIC * (float)g, &sn, &cs);
        // D' = -i*conj(W)*Q, conj(W) = (cs, sn) -> -i*conj(W) = (sn, -cs)
        float2 D = cmul(make_float2(sn, -cs), Q);
        // store conj(0.5*(S + D'))
        bufA[MAP(g)] = make_float2(0.5f * (S.x + D.x), -0.5f * (S.y + D.y));
    }
    __syncthreads();

    fft2048(bufA, bufB, tid);                      // conj(ifft)*2048 in bufA

    const float inv = 1.0f / 2048.0f;
    for (int n = tid; n < NC; n += TPB) {
        float2 r = bufA[MAP(n)];
        series[n] = make_float2(r.x * inv, -r.y * inv);
    }
}

// ------------------------------ twiddle init -------------------------------
__global__ void twiddle_init_kernel() {
    int k = blockIdx.x * blockDim.x + threadIdx.x;
    if (k < NC) {
        double ang = -2.0 * 3.14159265358979323846 * (double)k / (double)NC;
        g_tw[k] = make_float2((float)cos(ang), (float)sin(ang));
    }
}

// ------------------------------ transposes ---------------------------------
__global__ void transpose_fwd_kernel(const float* __restrict__ x) {
    __shared__ float tile[32][33];
    const int b  = blockIdx.z;
    const int c0 = blockIdx.x * 32;
    const int l0 = blockIdx.y * 32;
    const float* xb = x + (size_t)b * LEN * CH;
    float* sb = g_scratch + (size_t)b * CH * LEN;
    const int tx = threadIdx.x, ty = threadIdx.y;
#pragma unroll
    for (int k = 0; k < 32; k += 8)
        tile[ty + k][tx] = xb[(size_t)(l0 + ty + k) * CH + (c0 + tx)];
    __syncthreads();
#pragma unroll
    for (int k = 0; k < 32; k += 8)
        sb[(size_t)(c0 + ty + k) * LEN + (l0 + tx)] = tile[tx][ty + k];
}

__global__ void transpose_bwd_kernel(float* __restrict__ out) {
    __shared__ float tile[32][33];
    const int b  = blockIdx.z;
    const int l0 = blockIdx.x * 32;
    const int c0 = blockIdx.y * 32;
    const float* sb = g_scratch + (size_t)b * CH * LEN;
    float* ob = out + (size_t)b * LEN * CH;
    const int tx = threadIdx.x, ty = threadIdx.y;
#pragma unroll
    for (int k = 0; k < 32; k += 8)
        tile[ty + k][tx] = sb[(size_t)(c0 + ty + k) * LEN + (l0 + tx)];
    __syncthreads();
#pragma unroll
    for (int k = 0; k < 32; k += 8)
        ob[(size_t)(l0 + ty + k) * CH + (c0 + tx)] = tile[tx][ty + k];
}

// ------------------------------ launch -------------------------------------
extern "C" void kernel_launch(void* const* d_in, const int* in_sizes, int n_in,
                              void* d_out, int out_size) {
    const float* x = (const float*)d_in[0];
    float* out = (float*)d_out;

    twiddle_init_kernel<<<8, 256>>>();
    transpose_fwd_kernel<<<dim3(CH / 32, LEN / 32, BATCH), dim3(32, 8)>>>(x);
    fourier_block_kernel<<<BATCH * CH, TPB>>>();
    transpose_bwd_kernel<<<dim3(LEN / 32, CH / 32, BATCH), dim3(32, 8)>>>(out);
}

// round 2
// speedup vs baseline: 1.2949x; 1.2949x over previous
#include <cuda_runtime.h>
#include <math.h>

// ---------------------------------------------------------------------------
// FourierBlock: rfft(L=4096) -> top-16 |X| per (b,c) -> mask -> irfft
// x: [B=64, L=4096, C=128] f32
//
//   k0: twiddle init (double sincos -> f32 tables: FFT twiddles + half-twiddles)
//   k1: transpose [B,L,C] -> scratch [B,C,L]
//   k2: per-series kernel (1 CTA / series):
//        packed real FFT (complex 2048, radix 8,8,8,4; first pass reads gmem)
//        untangle -> |X|^2 (table twiddles), barrier-free warp top-16 + merge
//        sparse masked spectrum (16 bins) -> inverse untangle -> inverse FFT
//        (conj trick; last pass writes gmem directly with scale+conj)
//   k3: transpose scratch [B,C,L] -> out [B,L,C]
// ---------------------------------------------------------------------------

#define BATCH 64
#define LEN   4096
#define CH    128
#define NC    2048
#define NF    2049
#define TPB   256

#define MAP(i) ((i) + ((i) >> 4))
#define BUFSZ  (MAP(2048) + 8)

__device__ float  g_scratch[BATCH * CH * LEN];
__device__ float2 g_tw[NC];          // cis(-2*pi*k/2048)
__device__ float2 g_twh[NF];         // H[f] = (cos(pi f/2048), -sin(pi f/2048))

// ------------------------------ complex helpers ----------------------------
__device__ __forceinline__ float2 cmul(float2 a, float2 b) {
    return make_float2(fmaf(a.x, b.x, -a.y * b.y), fmaf(a.x, b.y, a.y * b.x));
}
__device__ __forceinline__ float2 cadd(float2 a, float2 b) {
    return make_float2(a.x + b.x, a.y + b.y);
}
__device__ __forceinline__ float2 csub(float2 a, float2 b) {
    return make_float2(a.x - b.x, a.y - b.y);
}

__device__ __forceinline__ void dft4(float2 v[4]) {
    float2 t0 = cadd(v[0], v[2]);
    float2 t1 = csub(v[0], v[2]);
    float2 t2 = cadd(v[1], v[3]);
    float2 t3 = csub(v[1], v[3]);
    v[0] = cadd(t0, t2);
    v[2] = csub(t0, t2);
    v[1] = make_float2(t1.x + t3.y, t1.y - t3.x);
    v[3] = make_float2(t1.x - t3.y, t1.y + t3.x);
}

__device__ __forceinline__ void dft8(float2 v[8]) {
    float2 e[4] = { v[0], v[2], v[4], v[6] };
    float2 o[4] = { v[1], v[3], v[5], v[7] };
    dft4(e);
    dft4(o);
    const float s = 0.70710678118654752f;
    o[1] = make_float2(s * (o[1].x + o[1].y), s * (o[1].y - o[1].x));
    o[2] = make_float2(o[2].y, -o[2].x);
    o[3] = make_float2(s * (o[3].y - o[3].x), -s * (o[3].x + o[3].y));
#pragma unroll
    for (int k = 0; k < 4; k++) {
        v[k]     = cadd(e[k], o[k]);
        v[k + 4] = csub(e[k], o[k]);
    }
}

// ------------------------------ Stockham passes ----------------------------
template <int NS>
__device__ __forceinline__ void pass8(const float2* __restrict__ src,
                                      float2* __restrict__ dst, int j) {
    float2 v[8];
#pragma unroll
    for (int r = 0; r < 8; r++) v[r] = src[MAP(j + r * 256)];
    if (NS > 1) {
        int k0 = (j & (NS - 1)) * (256 / NS);
#pragma unroll
        for (int r = 1; r < 8; r++) v[r] = cmul(v[r], __ldg(&g_tw[k0 * r]));
    }
    dft8(v);
    int idxD = ((j & ~(NS - 1)) << 3) + (j & (NS - 1));
#pragma unroll
    for (int r = 0; r < 8; r++) dst[MAP(idxD + r * NS)] = v[r];
}

// first pass reading directly from gmem (NS=1, no twiddle)
__device__ __forceinline__ void pass8_gmem(const float2* __restrict__ gsrc,
                                           float2* __restrict__ dst, int j) {
    float2 v[8];
#pragma unroll
    for (int r = 0; r < 8; r++) v[r] = gsrc[j + r * 256];
    dft8(v);
    int idxD = j << 3;
#pragma unroll
    for (int r = 0; r < 8; r++) dst[MAP(idxD + r)] = v[r];
}

__device__ __forceinline__ void pass4_512(const float2* __restrict__ src,
                                          float2* __restrict__ dst, int jj) {
    float2 v[4];
#pragma unroll
    for (int r = 0; r < 4; r++) v[r] = src[MAP(jj + r * 512)];
#pragma unroll
    for (int r = 1; r < 4; r++) v[r] = cmul(v[r], __ldg(&g_tw[jj * r]));
    dft4(v);
#pragma unroll
    for (int r = 0; r < 4; r++) dst[MAP(jj + r * 512)] = v[r];
}

// final inverse pass: dft4 then write gmem with conj + 1/2048 scale
__device__ __forceinline__ void pass4_512_out(const float2* __restrict__ src,
                                              float2* __restrict__ gdst, int jj) {
    float2 v[4];
#pragma unroll
    for (int r = 0; r < 4; r++) v[r] = src[MAP(jj + r * 512)];
#pragma unroll
    for (int r = 1; r < 4; r++) v[r] = cmul(v[r], __ldg(&g_tw[jj * r]));
    dft4(v);
    const float inv = 1.0f / 2048.0f;
#pragma unroll
    for (int r = 0; r < 4; r++)
        gdst[jj + r * 512] = make_float2(v[r].x * inv, -v[r].y * inv);
}

// ------------------------------ main kernel --------------------------------
__global__ void __launch_bounds__(TPB) fourier_block_kernel() {
    __shared__ float2 bufA[BUFSZ];
    __shared__ float2 bufB[BUFSZ];
    __shared__ float  candV[128];
    __shared__ int    candI[128];
    __shared__ int    keep[16];

    float* magF  = reinterpret_cast<float*>(bufB);    // aliases bufB (free window)
    float2* bufBl = bufB;                             // linear-indexed X' storage

    const int tid  = threadIdx.x;
    const int lane = tid & 31;
    const int w    = tid >> 5;
    float2* series = reinterpret_cast<float2*>(g_scratch) + (size_t)blockIdx.x * NC;

    // ---------------- forward FFT (gmem -> bufA) ----------------
    pass8_gmem(series, bufB, tid);
    __syncthreads();
    pass8<8>(bufB, bufA, tid);
    __syncthreads();
    pass8<64>(bufA, bufB, tid);
    __syncthreads();
    pass4_512(bufB, bufA, tid);
    pass4_512(bufB, bufA, tid + 256);
    __syncthreads();                                   // Z in bufA

    // ---------------- untangle -> |X|^2 into magF ----------------
    // NOTE: magF aliases bufB, whose contents are dead after the fft.
    for (int f = tid; f < NF; f += TPB) {
        float2 Zf = bufA[MAP(f & (NC - 1))];
        float2 Zn = bufA[MAP((NC - f) & (NC - 1))];
        float2 S  = make_float2(Zf.x + Zn.x, Zf.y - Zn.y);
        float2 D  = make_float2(Zf.x - Zn.x, Zf.y + Zn.y);
        float2 H  = __ldg(&g_twh[f]);
        float2 T  = cmul(make_float2(-H.y, H.x), D);   // i*H * D
        float2 X  = make_float2(0.5f * (S.x - T.x), 0.5f * (S.y - T.y));
        magF[f] = fmaf(X.x, X.x, X.y * X.y);
    }
    __syncthreads();

    // ---------------- barrier-free per-warp top-16 ----------------
    {
        float v[9];
#pragma unroll
        for (int i = 0; i < 8; i++) v[i] = magF[tid + 256 * i];
        v[8] = (tid == 0) ? magF[2048] : -1.0f;

        for (int it = 0; it < 16; it++) {
            float b = v[0];
            int   s = 0;
#pragma unroll
            for (int i = 1; i < 9; i++)
                if (v[i] > b) { b = v[i]; s = i; }
            int gi = tid + (s << 8);
#pragma unroll
            for (int o = 16; o; o >>= 1) {
                float ob = __shfl_xor_sync(0xffffffffu, b, o);
                int   oi = __shfl_xor_sync(0xffffffffu, gi, o);
                if (ob > b || (ob == b && oi < gi)) { b = ob; gi = oi; }
            }
            if (lane == 0) { candV[w * 16 + it] = b; candI[w * 16 + it] = gi; }
            if ((gi & 255) == tid) v[gi >> 8] = -1.0f;   // invalidate winner
        }
    }
    __syncthreads();

    // ---------------- warp-0 merge of 128 candidates ----------------
    if (w == 0) {
        float mv[4];
        int   mi[4];
#pragma unroll
        for (int q = 0; q < 4; q++) {
            mv[q] = candV[lane * 4 + q];
            mi[q] = candI[lane * 4 + q];
        }
        for (int it = 0; it < 16; it++) {
            float b  = mv[0];
            int   gi = mi[0];
#pragma unroll
            for (int q = 1; q < 4; q++)
                if (mv[q] > b || (mv[q] == b && mi[q] < gi)) { b = mv[q]; gi = mi[q]; }
#pragma unroll
            for (int o = 16; o; o >>= 1) {
                float ob = __shfl_xor_sync(0xffffffffu, b, o);
                int   oi = __shfl_xor_sync(0xffffffffu, gi, o);
                if (ob > b || (ob == b && oi < gi)) { b = ob; gi = oi; }
            }
            if (lane == 0) keep[it] = gi;
#pragma unroll
            for (int q = 0; q < 4; q++)
                if (mi[q] == gi) mv[q] = -1.0f;
        }
    }
    __syncthreads();

    // ---------------- masked spectrum X' (sparse) into bufBl ----------------
    {
        int kreg[16];
#pragma unroll
        for (int i = 0; i < 16; i++) kreg[i] = keep[i];
        for (int f = tid; f < NF; f += TPB) {
            bool kf = false;
#pragma unroll
            for (int i = 0; i < 16; i++) kf |= (kreg[i] == f);
            float2 X = make_float2(0.0f, 0.0f);
            if (kf) {
                float2 Zf = bufA[MAP(f & (NC - 1))];
                float2 Zn = bufA[MAP((NC - f) & (NC - 1))];
                float2 S  = make_float2(Zf.x + Zn.x, Zf.y - Zn.y);
                float2 D  = make_float2(Zf.x - Zn.x, Zf.y + Zn.y);
                float2 H  = __ldg(&g_twh[f]);
                float2 T  = cmul(make_float2(-H.y, H.x), D);
                X = make_float2(0.5f * (S.x - T.x), 0.5f * (S.y - T.y));
            }
            bufBl[f] = X;
        }
    }
    __syncthreads();

    // ---------------- inverse untangle -> conj(Z') into bufA ----------------
    for (int g = tid; g < NC; g += TPB) {
        float2 Xg = bufBl[g];
        float2 Xn = bufBl[NC - g];
        float2 S  = make_float2(Xg.x + Xn.x, Xg.y - Xn.y);       // Xg + conj(Xn)
        float2 Q  = make_float2(Xn.x - Xg.x, -Xn.y - Xg.y);      // conj(Xn) - Xg
        float2 H  = __ldg(&g_twh[g]);
        float2 D  = cmul(make_float2(-H.y, -H.x), Q);            // -i*conj(H) * Q
        bufA[MAP(g)] = make_float2(0.5f * (S.x + D.x), -0.5f * (S.y + D.y));
    }
    __syncthreads();

    // ---------------- inverse FFT via conj trick (bufA -> gmem) ----------------
    pass8<1>(bufA, bufB, tid);
    __syncthreads();
    pass8<8>(bufB, bufA, tid);
    __syncthreads();
    pass8<64>(bufA, bufB, tid);
    __syncthreads();
    pass4_512_out(bufB, series, tid);
    pass4_512_out(bufB, series, tid + 256);
}

// ------------------------------ twiddle init -------------------------------
__global__ void twiddle_init_kernel() {
    int k = blockIdx.x * blockDim.x + threadIdx.x;
    const double PI = 3.14159265358979323846;
    if (k < NC) {
        double ang = -2.0 * PI * (double)k / (double)NC;
        g_tw[k] = make_float2((float)cos(ang), (float)sin(ang));
    }
    if (k < NF) {
        double th = PI * (double)k / (double)NC;
        g_twh[k] = make_float2((float)cos(th), (float)(-sin(th)));
    }
}

// ------------------------------ transposes ---------------------------------
__global__ void transpose_fwd_kernel(const float* __restrict__ x) {
    __shared__ float tile[32][33];
    const int b  = blockIdx.z;
    const int c0 = blockIdx.x * 32;
    const int l0 = blockIdx.y * 32;
    const float* xb = x + (size_t)b * LEN * CH;
    float* sb = g_scratch + (size_t)b * CH * LEN;
    const int tx = threadIdx.x, ty = threadIdx.y;
#pragma unroll
    for (int k = 0; k < 32; k += 8)
        tile[ty + k][tx] = xb[(size_t)(l0 + ty + k) * CH + (c0 + tx)];
    __syncthreads();
#pragma unroll
    for (int k = 0; k < 32; k += 8)
        sb[(size_t)(c0 + ty + k) * LEN + (l0 + tx)] = tile[tx][ty + k];
}

__global__ void transpose_bwd_kernel(float* __restrict__ out) {
    __shared__ float tile[32][33];
    const int b  = blockIdx.z;
    const int l0 = blockIdx.x * 32;
    const int c0 = blockIdx.y * 32;
    const float* sb = g_scratch + (size_t)b * CH * LEN;
    float* ob = out + (size_t)b * LEN * CH;
    const int tx = threadIdx.x, ty = threadIdx.y;
#pragma unroll
    for (int k = 0; k < 32; k += 8)
        tile[ty + k][tx] = sb[(size_t)(c0 + ty + k) * LEN + (l0 + tx)];
    __syncthreads();
#pragma unroll
    for (int k = 0; k < 32; k += 8)
        ob[(size_t)(l0 + ty + k) * CH + (c0 + tx)] = tile[tx][ty + k];
}

// ------------------------------ launch -------------------------------------
extern "C" void kernel_launch(void* const* d_in, const int* in_sizes, int n_in,
                              void* d_out, int out_size) {
    const float* x = (const float*)d_in[0];
    float* out = (float*)d_out;

    twiddle_init_kernel<<<9, 256>>>();
    transpose_fwd_kernel<<<dim3(CH / 32, LEN / 32, BATCH), dim3(32, 8)>>>(x);
    fourier_block_kernel<<<BATCH * CH, TPB>>>();
    transpose_bwd_kernel<<<dim3(LEN / 32, CH / 32, BATCH), dim3(32, 8)>>>(out);
}

// round 3
// speedup vs baseline: 1.6188x; 1.2502x over previous
#include <cuda_runtime.h>
#include <math.h>

// ---------------------------------------------------------------------------
// FourierBlock: rfft(L=4096) -> top-16 |X| per (b,c) -> mask -> irfft
// x: [B=64, L=4096, C=128] f32
//
//   k0: twiddle init
//   k1: transpose [B,L,C] -> scratch [B,C,L]
//   k2: per-series kernel (1 CTA / series):
//        packed real FFT (complex 2048, radix 8,8,8,4; 1st pass reads gmem)
//        pair-fused untangle -> |X|^2 in REGISTERS (no smem mag array)
//        barrier-free warp top-16 + warp0 merge
//        pair-fused mask + inverse untangle, in-place, barrier-free
//        inverse FFT (conj trick; last pass writes gmem with scale+conj)
//   k3: transpose scratch [B,C,L] -> out [B,L,C]
//
// Pair algebra (one S,D,T per pair serves both bins):
//   X[f]      = 0.5*(S - T),          T = i*H[f]*D
//   X[2048-f] = conj(0.5*(S + T))
//   Z'[g]      = 0.5*(S~ + D~),       D~ = -i*conj(H[g])*Q
//   Z'[2048-g] = conj(0.5*(S~ - D~))
// ---------------------------------------------------------------------------

#define BATCH 64
#define LEN   4096
#define CH    128
#define NC    2048
#define NF    2049
#define TPB   256

#define MAP(i) ((i) + ((i) >> 4))
#define BUFSZ  (MAP(2048) + 8)

__device__ float  g_scratch[BATCH * CH * LEN];
__device__ float2 g_tw[NC];          // cis(-2*pi*k/2048)
__device__ float2 g_twh[NF];         // H[f] = cis(-pi*f/2048)

// ------------------------------ complex helpers ----------------------------
__device__ __forceinline__ float2 cmul(float2 a, float2 b) {
    return make_float2(fmaf(a.x, b.x, -a.y * b.y), fmaf(a.x, b.y, a.y * b.x));
}
__device__ __forceinline__ float2 cadd(float2 a, float2 b) {
    return make_float2(a.x + b.x, a.y + b.y);
}
__device__ __forceinline__ float2 csub(float2 a, float2 b) {
    return make_float2(a.x - b.x, a.y - b.y);
}

__device__ __forceinline__ void dft4(float2 v[4]) {
    float2 t0 = cadd(v[0], v[2]);
    float2 t1 = csub(v[0], v[2]);
    float2 t2 = cadd(v[1], v[3]);
    float2 t3 = csub(v[1], v[3]);
    v[0] = cadd(t0, t2);
    v[2] = csub(t0, t2);
    v[1] = make_float2(t1.x + t3.y, t1.y - t3.x);
    v[3] = make_float2(t1.x - t3.y, t1.y + t3.x);
}

__device__ __forceinline__ void dft8(float2 v[8]) {
    float2 e[4] = { v[0], v[2], v[4], v[6] };
    float2 o[4] = { v[1], v[3], v[5], v[7] };
    dft4(e);
    dft4(o);
    const float s = 0.70710678118654752f;
    o[1] = make_float2(s * (o[1].x + o[1].y), s * (o[1].y - o[1].x));
    o[2] = make_float2(o[2].y, -o[2].x);
    o[3] = make_float2(s * (o[3].y - o[3].x), -s * (o[3].x + o[3].y));
#pragma unroll
    for (int k = 0; k < 4; k++) {
        v[k]     = cadd(e[k], o[k]);
        v[k + 4] = csub(e[k], o[k]);
    }
}

// ------------------------------ Stockham passes ----------------------------
template <int NS>
__device__ __forceinline__ void pass8(const float2* __restrict__ src,
                                      float2* __restrict__ dst, int j) {
    float2 v[8];
#pragma unroll
    for (int r = 0; r < 8; r++) v[r] = src[MAP(j + r * 256)];
    if (NS > 1) {
        int k0 = (j & (NS - 1)) * (256 / NS);
#pragma unroll
        for (int r = 1; r < 8; r++) v[r] = cmul(v[r], __ldg(&g_tw[k0 * r]));
    }
    dft8(v);
    int idxD = ((j & ~(NS - 1)) << 3) + (j & (NS - 1));
#pragma unroll
    for (int r = 0; r < 8; r++) dst[MAP(idxD + r * NS)] = v[r];
}

__device__ __forceinline__ void pass8_gmem(const float2* __restrict__ gsrc,
                                           float2* __restrict__ dst, int j) {
    float2 v[8];
#pragma unroll
    for (int r = 0; r < 8; r++) v[r] = gsrc[j + r * 256];
    dft8(v);
    int idxD = j << 3;
#pragma unroll
    for (int r = 0; r < 8; r++) dst[MAP(idxD + r)] = v[r];
}

__device__ __forceinline__ void pass4_512(const float2* __restrict__ src,
                                          float2* __restrict__ dst, int jj) {
    float2 v[4];
#pragma unroll
    for (int r = 0; r < 4; r++) v[r] = src[MAP(jj + r * 512)];
#pragma unroll
    for (int r = 1; r < 4; r++) v[r] = cmul(v[r], __ldg(&g_tw[jj * r]));
    dft4(v);
#pragma unroll
    for (int r = 0; r < 4; r++) dst[MAP(jj + r * 512)] = v[r];
}

__device__ __forceinline__ void pass4_512_out(const float2* __restrict__ src,
                                              float2* __restrict__ gdst, int jj) {
    float2 v[4];
#pragma unroll
    for (int r = 0; r < 4; r++) v[r] = src[MAP(jj + r * 512)];
#pragma unroll
    for (int r = 1; r < 4; r++) v[r] = cmul(v[r], __ldg(&g_tw[jj * r]));
    dft4(v);
    const float inv = 1.0f / 2048.0f;
#pragma unroll
    for (int r = 0; r < 4; r++)
        gdst[jj + r * 512] = make_float2(v[r].x * inv, -v[r].y * inv);
}

// bin index for thread t, slot i (i<4: bins 0..1023; i>=4: bins 1025..2048 + 1024)
__device__ __forceinline__ int slot_bin(int t, int i) {
    return (i < 4) ? (t + (i << 8)) : (2048 - (t + ((i - 4) << 8)));
}

// ------------------------------ main kernel --------------------------------
__global__ void __launch_bounds__(TPB, 6) fourier_block_kernel() {
    __shared__ float2 bufA[BUFSZ];
    __shared__ float2 bufB[BUFSZ];
    __shared__ float  candV[128];
    __shared__ int    candI[128];
    __shared__ int    keep[16];

    const int tid  = threadIdx.x;
    const int lane = tid & 31;
    const int w    = tid >> 5;
    float2* series = reinterpret_cast<float2*>(g_scratch) + (size_t)blockIdx.x * NC;

    // ---------------- forward FFT (gmem -> bufA) ----------------
    pass8_gmem(series, bufB, tid);
    __syncthreads();
    pass8<8>(bufB, bufA, tid);
    __syncthreads();
    pass8<64>(bufA, bufB, tid);
    __syncthreads();
    pass4_512(bufB, bufA, tid);
    pass4_512(bufB, bufA, tid + 256);
    __syncthreads();                                   // Z in bufA

    // ---------------- pairs pass 1: |X|^2 into registers ----------------
    float v[9];
#pragma unroll
    for (int q = 0; q < 4; q++) {
        int p = tid + (q << 8);                        // 0..1023
        float2 Zf = bufA[MAP(p)];
        float2 Zn = bufA[MAP((NC - p) & (NC - 1))];
        float2 S  = make_float2(Zf.x + Zn.x, Zf.y - Zn.y);
        float2 D  = make_float2(Zf.x - Zn.x, Zf.y + Zn.y);
        float2 H  = __ldg(&g_twh[p]);
        float2 T  = cmul(make_float2(-H.y, H.x), D);   // i*H*D
        float2 XA = make_float2(S.x - T.x, S.y - T.y); // 2*X[p]
        float2 XB = make_float2(S.x + T.x, S.y + T.y); // 2*conj(X[2048-p])
        v[q]     = fmaf(XA.x, XA.x, XA.y * XA.y);      // mag^2 * 4 (order-preserving)
        v[q + 4] = fmaf(XB.x, XB.x, XB.y * XB.y);
    }
    v[8] = -1.0f;
    if (tid == 0) {                                    // bin 1024 (self-pair)
        float2 Zf = bufA[MAP(1024)];
        float2 S  = make_float2(2.0f * Zf.x, 0.0f);
        float2 D  = make_float2(0.0f, 2.0f * Zf.y);
        float2 H  = __ldg(&g_twh[1024]);
        float2 T  = cmul(make_float2(-H.y, H.x), D);
        float2 XA = make_float2(S.x - T.x, S.y - T.y);
        v[8] = fmaf(XA.x, XA.x, XA.y * XA.y);
    }

    // ---------------- per-warp top-16 (barrier-free) ----------------
    for (int it = 0; it < 16; it++) {
        float b    = v[0];
        int   bbin = tid;                              // slot_bin(tid,0)
#pragma unroll
        for (int i = 1; i < 9; i++) {
            int bi = slot_bin(tid, i);
            if (v[i] > b || (v[i] == b && bi < bbin)) { b = v[i]; bbin = bi; }
        }
#pragma unroll
        for (int o = 16; o; o >>= 1) {
            float ob = __shfl_xor_sync(0xffffffffu, b, o);
            int   oi = __shfl_xor_sync(0xffffffffu, bbin, o);
            if (ob > b || (ob == b && oi < bbin)) { b = ob; bbin = oi; }
        }
        if (lane == 0) { candV[w * 16 + it] = b; candI[w * 16 + it] = bbin; }
        // invalidate winner in its owner's registers
        int ot, os;
        if (bbin < 1024) { ot = bbin & 255; os = bbin >> 8; }
        else             { int p2 = 2048 - bbin; ot = p2 & 255; os = 4 + (p2 >> 8); }
        if (ot == tid) v[os] = -1.0f;
    }
    __syncthreads();

    // ---------------- warp-0 merge of 128 candidates ----------------
    if (w == 0) {
        float mv[4];
        int   mi[4];
#pragma unroll
        for (int q = 0; q < 4; q++) {
            mv[q] = candV[lane * 4 + q];
            mi[q] = candI[lane * 4 + q];
        }
        for (int it = 0; it < 16; it++) {
            float b  = mv[0];
            int   gi = mi[0];
#pragma unroll
            for (int q = 1; q < 4; q++)
                if (mv[q] > b || (mv[q] == b && mi[q] < gi)) { b = mv[q]; gi = mi[q]; }
#pragma unroll
            for (int o = 16; o; o >>= 1) {
                float ob = __shfl_xor_sync(0xffffffffu, b, o);
                int   oi = __shfl_xor_sync(0xffffffffu, gi, o);
                if (ob > b || (ob == b && oi < gi)) { b = ob; gi = oi; }
            }
            if (lane == 0) keep[it] = gi;
#pragma unroll
            for (int q = 0; q < 4; q++)
                if (mi[q] == gi) mv[q] = -1.0f;
        }
    }
    __syncthreads();

    // ------- pairs pass 2: mask + inverse untangle, in place, no sync -------
    {
        int kreg[16];
#pragma unroll
        for (int i = 0; i < 16; i++) kreg[i] = keep[i];

#pragma unroll
        for (int q = 0; q < 5; q++) {
            int p = tid + (q << 8);                    // 0..1023 (+1024 on tid 0)
            if (q == 4 && tid != 0) break;
            if (q == 4) p = 1024;
            int pm = (NC - p) & (NC - 1);
            float2 Zf = bufA[MAP(p)];
            float2 Zn = bufA[MAP(pm)];
            float2 S  = make_float2(Zf.x + Zn.x, Zf.y - Zn.y);
            float2 D  = make_float2(Zf.x - Zn.x, Zf.y + Zn.y);
            float2 H  = __ldg(&g_twh[p]);
            float2 T  = cmul(make_float2(-H.y, H.x), D);
            // X'[p] and X'[2048-p] (masked)
            bool ka = false, kb = false;
            int binB = 2048 - p;
#pragma unroll
            for (int i = 0; i < 16; i++) {
                ka |= (kreg[i] == p);
                kb |= (kreg[i] == binB);
            }
            float2 A  = ka ? make_float2(0.5f * (S.x - T.x), 0.5f * (S.y - T.y))
                           : make_float2(0.0f, 0.0f);
            float2 Bc = kb ? make_float2(0.5f * (S.x + T.x), 0.5f * (S.y + T.y))
                           : make_float2(0.0f, 0.0f);   // Bc = conj(X'[2048-p])
            // inverse untangle: S~ = A + Bc (since conj(X'[2048-p]) = Bc... note
            // X'[2048-p] = conj(Bc), so conj(X'[2048-p]) = Bc)
            float2 St = make_float2(A.x + Bc.x, A.y + Bc.y);
            float2 Q  = make_float2(Bc.x - A.x, Bc.y - A.y);
            float2 Dt = cmul(make_float2(-H.y, -H.x), Q);     // -i*conj(H)*Q
            // store conj(Z'[p]) and conj(Z'[2048-p])
            bufA[MAP(p)] = make_float2(0.5f * (St.x + Dt.x), -0.5f * (St.y + Dt.y));
            if (p != 0 && p != 1024)
                bufA[MAP(binB)] = make_float2(0.5f * (St.x - Dt.x), 0.5f * (St.y - Dt.y));
        }
    }
    __syncthreads();

    // ---------------- inverse FFT via conj trick (bufA -> gmem) ----------------
    pass8<1>(bufA, bufB, tid);
    __syncthreads();
    pass8<8>(bufB, bufA, tid);
    __syncthreads();
    pass8<64>(bufA, bufB, tid);
    __syncthreads();
    pass4_512_out(bufB, series, tid);
    pass4_512_out(bufB, series, tid + 256);
}

// ------------------------------ twiddle init -------------------------------
__global__ void twiddle_init_kernel() {
    int k = blockIdx.x * blockDim.x + threadIdx.x;
    const double PI = 3.14159265358979323846;
    if (k < NC) {
        double ang = -2.0 * PI * (double)k / (double)NC;
        g_tw[k] = make_float2((float)cos(ang), (float)sin(ang));
    }
    if (k < NF) {
        double th = PI * (double)k / (double)NC;
        g_twh[k] = make_float2((float)cos(th), (float)(-sin(th)));
    }
}

// ------------------------------ transposes ---------------------------------
__global__ void transpose_fwd_kernel(const float* __restrict__ x) {
    __shared__ float tile[32][33];
    const int b  = blockIdx.z;
    const int c0 = blockIdx.x * 32;
    const int l0 = blockIdx.y * 32;
    const float* xb = x + (size_t)b * LEN * CH;
    float* sb = g_scratch + (size_t)b * CH * LEN;
    const int tx = threadIdx.x, ty = threadIdx.y;
#pragma unroll
    for (int k = 0; k < 32; k += 8)
        tile[ty + k][tx] = xb[(size_t)(l0 + ty + k) * CH + (c0 + tx)];
    __syncthreads();
#pragma unroll
    for (int k = 0; k < 32; k += 8)
        sb[(size_t)(c0 + ty + k) * LEN + (l0 + tx)] = tile[tx][ty + k];
}

__global__ void transpose_bwd_kernel(float* __restrict__ out) {
    __shared__ float tile[32][33];
    const int b  = blockIdx.z;
    const int l0 = blockIdx.x * 32;
    const int c0 = blockIdx.y * 32;
    const float* sb = g_scratch + (size_t)b * CH * LEN;
    float* ob = out + (size_t)b * LEN * CH;
    const int tx = threadIdx.x, ty = threadIdx.y;
#pragma unroll
    for (int k = 0; k < 32; k += 8)
        tile[ty + k][tx] = sb[(size_t)(c0 + ty + k) * LEN + (l0 + tx)];
    __syncthreads();
#pragma unroll
    for (int k = 0; k < 32; k += 8)
        ob[(size_t)(l0 + ty + k) * CH + (c0 + tx)] = tile[tx][ty + k];
}

// ------------------------------ launch -------------------------------------
extern "C" void kernel_launch(void* const* d_in, const int* in_sizes, int n_in,
                              void* d_out, int out_size) {
    const float* x = (const float*)d_in[0];
    float* out = (float*)d_out;

    twiddle_init_kernel<<<9, 256>>>();
    transpose_fwd_kernel<<<dim3(CH / 32, LEN / 32, BATCH), dim3(32, 8)>>>(x);
    fourier_block_kernel<<<BATCH * CH, TPB>>>();
    transpose_bwd_kernel<<<dim3(LEN / 32, CH / 32, BATCH), dim3(32, 8)>>>(out);
}

// round 4
// speedup vs baseline: 1.8057x; 1.1155x over previous
#include <cuda_runtime.h>
#include <math.h>

// ---------------------------------------------------------------------------
// FourierBlock: rfft(L=4096) -> top-16 |X| per (b,c) -> mask -> irfft
// x: [B=64, L=4096, C=128] f32
//
//   k0: twiddle init
//   k1: transpose [B,L,C] -> scratch [B,C,L]   (128x32 tiles, MLP=16)
//   k2: per-series kernel (1 CTA / series):
//        packed real FFT (complex 2048, radix 8,8,8,4; 1st pass reads gmem)
//        pair-fused untangle -> |X|^2 bits in registers
//        redux.sync-based warp top-16 + warp0 merge
//        pair-fused mask + inverse untangle, in place
//        inverse FFT (conj trick; last pass writes gmem with scale+conj)
//   k3: transpose scratch [B,C,L] -> out [B,L,C]
// ---------------------------------------------------------------------------

#define BATCH 64
#define LEN   4096
#define CH    128
#define NC    2048
#define NF    2049
#define TPB   256

#define MAP(i) ((i) + ((i) >> 4))
#define BUFSZ  (MAP(2048) + 8)

__device__ float  g_scratch[BATCH * CH * LEN];
__device__ float2 g_tw[NC];          // cis(-2*pi*k/2048)
__device__ float2 g_twh[NF];         // H[f] = cis(-pi*f/2048)

// ------------------------------ warp redux ---------------------------------
__device__ __forceinline__ unsigned redux_max_u32(unsigned v) {
    unsigned r;
    asm("redux.sync.max.u32 %0, %1, 0xffffffff;" : "=r"(r) : "r"(v));
    return r;
}
__device__ __forceinline__ unsigned redux_min_u32(unsigned v) {
    unsigned r;
    asm("redux.sync.min.u32 %0, %1, 0xffffffff;" : "=r"(r) : "r"(v));
    return r;
}

// ------------------------------ complex helpers ----------------------------
__device__ __forceinline__ float2 cmul(float2 a, float2 b) {
    return make_float2(fmaf(a.x, b.x, -a.y * b.y), fmaf(a.x, b.y, a.y * b.x));
}
__device__ __forceinline__ float2 cadd(float2 a, float2 b) {
    return make_float2(a.x + b.x, a.y + b.y);
}
__device__ __forceinline__ float2 csub(float2 a, float2 b) {
    return make_float2(a.x - b.x, a.y - b.y);
}

__device__ __forceinline__ void dft4(float2 v[4]) {
    float2 t0 = cadd(v[0], v[2]);
    float2 t1 = csub(v[0], v[2]);
    float2 t2 = cadd(v[1], v[3]);
    float2 t3 = csub(v[1], v[3]);
    v[0] = cadd(t0, t2);
    v[2] = csub(t0, t2);
    v[1] = make_float2(t1.x + t3.y, t1.y - t3.x);
    v[3] = make_float2(t1.x - t3.y, t1.y + t3.x);
}

__device__ __forceinline__ void dft8(float2 v[8]) {
    float2 e[4] = { v[0], v[2], v[4], v[6] };
    float2 o[4] = { v[1], v[3], v[5], v[7] };
    dft4(e);
    dft4(o);
    const float s = 0.70710678118654752f;
    o[1] = make_float2(s * (o[1].x + o[1].y), s * (o[1].y - o[1].x));
    o[2] = make_float2(o[2].y, -o[2].x);
    o[3] = make_float2(s * (o[3].y - o[3].x), -s * (o[3].x + o[3].y));
#pragma unroll
    for (int k = 0; k < 4; k++) {
        v[k]     = cadd(e[k], o[k]);
        v[k + 4] = csub(e[k], o[k]);
    }
}

// ------------------------------ Stockham passes ----------------------------
template <int NS>
__device__ __forceinline__ void pass8(const float2* __restrict__ src,
                                      float2* __restrict__ dst, int j) {
    float2 v[8];
#pragma unroll
    for (int r = 0; r < 8; r++) v[r] = src[MAP(j + r * 256)];
    if (NS > 1) {
        int k0 = (j & (NS - 1)) * (256 / NS);
#pragma unroll
        for (int r = 1; r < 8; r++) v[r] = cmul(v[r], __ldg(&g_tw[k0 * r]));
    }
    dft8(v);
    int idxD = ((j & ~(NS - 1)) << 3) + (j & (NS - 1));
#pragma unroll
    for (int r = 0; r < 8; r++) dst[MAP(idxD + r * NS)] = v[r];
}

__device__ __forceinline__ void pass8_gmem(const float2* __restrict__ gsrc,
                                           float2* __restrict__ dst, int j) {
    float2 v[8];
#pragma unroll
    for (int r = 0; r < 8; r++) v[r] = gsrc[j + r * 256];
    dft8(v);
    int idxD = j << 3;
#pragma unroll
    for (int r = 0; r < 8; r++) dst[MAP(idxD + r)] = v[r];
}

__device__ __forceinline__ void pass4_512(const float2* __restrict__ src,
                                          float2* __restrict__ dst, int jj) {
    float2 v[4];
#pragma unroll
    for (int r = 0; r < 4; r++) v[r] = src[MAP(jj + r * 512)];
#pragma unroll
    for (int r = 1; r < 4; r++) v[r] = cmul(v[r], __ldg(&g_tw[jj * r]));
    dft4(v);
#pragma unroll
    for (int r = 0; r < 4; r++) dst[MAP(jj + r * 512)] = v[r];
}

__device__ __forceinline__ void pass4_512_out(const float2* __restrict__ src,
                                              float2* __restrict__ gdst, int jj) {
    float2 v[4];
#pragma unroll
    for (int r = 0; r < 4; r++) v[r] = src[MAP(jj + r * 512)];
#pragma unroll
    for (int r = 1; r < 4; r++) v[r] = cmul(v[r], __ldg(&g_tw[jj * r]));
    dft4(v);
    const float inv = 1.0f / 2048.0f;
#pragma unroll
    for (int r = 0; r < 4; r++)
        gdst[jj + r * 512] = make_float2(v[r].x * inv, -v[r].y * inv);
}

// bin index for thread t, slot i
__device__ __forceinline__ int slot_bin(int t, int i) {
    return (i < 4) ? (t + (i << 8)) : (2048 - (t + ((i - 4) << 8)));
}

// ------------------------------ main kernel --------------------------------
__global__ void __launch_bounds__(TPB, 6) fourier_block_kernel() {
    __shared__ float2   bufA[BUFSZ];
    __shared__ float2   bufB[BUFSZ];
    __shared__ unsigned candV[128];
    __shared__ unsigned candI[128];
    __shared__ int      keep[16];

    const int tid  = threadIdx.x;
    const int lane = tid & 31;
    const int w    = tid >> 5;
    float2* series = reinterpret_cast<float2*>(g_scratch) + (size_t)blockIdx.x * NC;

    // ---------------- forward FFT (gmem -> bufA) ----------------
    pass8_gmem(series, bufB, tid);
    __syncthreads();
    pass8<8>(bufB, bufA, tid);
    __syncthreads();
    pass8<64>(bufA, bufB, tid);
    __syncthreads();
    pass4_512(bufB, bufA, tid);
    pass4_512(bufB, bufA, tid + 256);
    __syncthreads();                                   // Z in bufA

    // ---------------- pairs pass 1: |X|^2 bits into registers ----------------
    unsigned fb[9];
#pragma unroll
    for (int q = 0; q < 4; q++) {
        int p = tid + (q << 8);                        // 0..1023
        float2 Zf = bufA[MAP(p)];
        float2 Zn = bufA[MAP((NC - p) & (NC - 1))];
        float2 S  = make_float2(Zf.x + Zn.x, Zf.y - Zn.y);
        float2 D  = make_float2(Zf.x - Zn.x, Zf.y + Zn.y);
        float2 H  = __ldg(&g_twh[p]);
        float2 T  = cmul(make_float2(-H.y, H.x), D);   // i*H*D
        float2 XA = make_float2(S.x - T.x, S.y - T.y); // 2*X[p]
        float2 XB = make_float2(S.x + T.x, S.y + T.y); // 2*conj(X[2048-p])
        fb[q]     = __float_as_uint(fmaf(XA.x, XA.x, XA.y * XA.y));
        fb[q + 4] = __float_as_uint(fmaf(XB.x, XB.x, XB.y * XB.y));
    }
    fb[8] = 0u;
    unsigned alive = 0x0FFu;
    if (tid == 0) {                                    // bin 1024 (self-pair)
        float2 Zf = bufA[MAP(1024)];
        float2 S  = make_float2(2.0f * Zf.x, 0.0f);
        float2 D  = make_float2(0.0f, 2.0f * Zf.y);
        float2 H  = __ldg(&g_twh[1024]);
        float2 T  = cmul(make_float2(-H.y, H.x), D);
        float2 XA = make_float2(S.x - T.x, S.y - T.y);
        fb[8] = __float_as_uint(fmaf(XA.x, XA.x, XA.y * XA.y));
        alive = 0x1FFu;
    }

    // ---------------- per-warp top-16 via redux ----------------
    for (int it = 0; it < 16; it++) {
        unsigned mb = 0u;
#pragma unroll
        for (int i = 0; i < 9; i++) {
            unsigned fi = ((alive >> i) & 1u) ? fb[i] : 0u;
            mb = (fi > mb) ? fi : mb;
        }
        unsigned best = redux_max_u32(mb);
        unsigned mybin = 0xFFFFFFFFu;
        int myslot = -1;
        if (mb == best) {
#pragma unroll
            for (int i = 0; i < 9; i++) {
                if (((alive >> i) & 1u) && fb[i] == best) {
                    unsigned bn = (unsigned)slot_bin(tid, i);
                    if (bn < mybin) { mybin = bn; myslot = i; }
                }
            }
        }
        unsigned wbin = redux_min_u32(mybin);
        if (lane == 0) { candV[w * 16 + it] = best; candI[w * 16 + it] = wbin; }
        if (mybin == wbin && myslot >= 0) alive &= ~(1u << myslot);
    }
    __syncthreads();

    // ---------------- warp-0 merge of 128 candidates via redux ----------------
    if (w == 0) {
        unsigned fv[4], bn4[4];
#pragma unroll
        for (int q = 0; q < 4; q++) {
            fv[q]  = candV[lane * 4 + q];
            bn4[q] = candI[lane * 4 + q];
        }
        unsigned malive = 0xFu;
        for (int it = 0; it < 16; it++) {
            unsigned mb = 0u;
#pragma unroll
            for (int q = 0; q < 4; q++) {
                unsigned fi = ((malive >> q) & 1u) ? fv[q] : 0u;
                mb = (fi > mb) ? fi : mb;
            }
            unsigned best = redux_max_u32(mb);
            unsigned mybin = 0xFFFFFFFFu;
            int myslot = -1;
            if (mb == best) {
#pragma unroll
                for (int q = 0; q < 4; q++) {
                    if (((malive >> q) & 1u) && fv[q] == best && bn4[q] < mybin) {
                        mybin = bn4[q];
                        myslot = q;
                    }
                }
            }
            unsigned wbin = redux_min_u32(mybin);
            if (lane == 0) keep[it] = (int)wbin;
            if (mybin == wbin && myslot >= 0) malive &= ~(1u << myslot);
        }
    }
    __syncthreads();

    // ------- pairs pass 2: mask + inverse untangle, in place, no sync -------
    {
        int kreg[16];
#pragma unroll
        for (int i = 0; i < 16; i++) kreg[i] = keep[i];

#pragma unroll
        for (int q = 0; q < 5; q++) {
            int p = tid + (q << 8);
            if (q == 4 && tid != 0) break;
            if (q == 4) p = 1024;
            int pm = (NC - p) & (NC - 1);
            float2 Zf = bufA[MAP(p)];
            float2 Zn = bufA[MAP(pm)];
            float2 S  = make_float2(Zf.x + Zn.x, Zf.y - Zn.y);
            float2 D  = make_float2(Zf.x - Zn.x, Zf.y + Zn.y);
            float2 H  = __ldg(&g_twh[p]);
            float2 T  = cmul(make_float2(-H.y, H.x), D);
            bool ka = false, kb = false;
            int binB = 2048 - p;
#pragma unroll
            for (int i = 0; i < 16; i++) {
                ka |= (kreg[i] == p);
                kb |= (kreg[i] == binB);
            }
            float2 A  = ka ? make_float2(0.5f * (S.x - T.x), 0.5f * (S.y - T.y))
                           : make_float2(0.0f, 0.0f);
            float2 Bc = kb ? make_float2(0.5f * (S.x + T.x), 0.5f * (S.y + T.y))
                           : make_float2(0.0f, 0.0f);   // Bc = conj(X'[2048-p])
            float2 St = make_float2(A.x + Bc.x, A.y + Bc.y);
            float2 Q  = make_float2(Bc.x - A.x, Bc.y - A.y);
            float2 Dt = cmul(make_float2(-H.y, -H.x), Q); // -i*conj(H)*Q
            bufA[MAP(p)] = make_float2(0.5f * (St.x + Dt.x), -0.5f * (St.y + Dt.y));
            if (p != 0 && p != 1024)
                bufA[MAP(binB)] = make_float2(0.5f * (St.x - Dt.x), 0.5f * (St.y - Dt.y));
        }
    }
    __syncthreads();

    // ---------------- inverse FFT via conj trick (bufA -> gmem) ----------------
    pass8<1>(bufA, bufB, tid);
    __syncthreads();
    pass8<8>(bufB, bufA, tid);
    __syncthreads();
    pass8<64>(bufA, bufB, tid);
    __syncthreads();
    pass4_512_out(bufB, series, tid);
    pass4_512_out(bufB, series, tid + 256);
}

// ------------------------------ twiddle init -------------------------------
__global__ void twiddle_init_kernel() {
    int k = blockIdx.x * blockDim.x + threadIdx.x;
    const double PI = 3.14159265358979323846;
    if (k < NC) {
        double ang = -2.0 * PI * (double)k / (double)NC;
        g_tw[k] = make_float2((float)cos(ang), (float)sin(ang));
    }
    if (k < NF) {
        double th = PI * (double)k / (double)NC;
        g_twh[k] = make_float2((float)cos(th), (float)(-sin(th)));
    }
}

// ------------------------------ transposes (128x32 tiles) ------------------
__global__ void __launch_bounds__(256) transpose_fwd_kernel(const float* __restrict__ x) {
    __shared__ float tile[128][33];
    const int b  = blockIdx.z;
    const int c0 = blockIdx.x * 32;
    const int l0 = blockIdx.y * 128;
    const float* xb = x + (size_t)b * LEN * CH;
    float* sb = g_scratch + (size_t)b * CH * LEN;
    const int lane = threadIdx.x & 31;
    const int wrp  = threadIdx.x >> 5;     // 0..7
#pragma unroll
    for (int k = 0; k < 16; k++) {
        int l = wrp + k * 8;
        tile[l][lane] = xb[(size_t)(l0 + l) * CH + (c0 + lane)];
    }
    __syncthreads();
#pragma unroll
    for (int m = 0; m < 4; m++) {
        int c = wrp * 4 + m;
#pragma unroll
        for (int k = 0; k < 4; k++) {
            int l = lane + k * 32;
            sb[(size_t)(c0 + c) * LEN + (l0 + l)] = tile[l][c];
        }
    }
}

__global__ void __launch_bounds__(256) transpose_bwd_kernel(float* __restrict__ out) {
    __shared__ float tile[128][33];
    const int b  = blockIdx.z;
    const int c0 = blockIdx.x * 32;
    const int l0 = blockIdx.y * 128;
    const float* sb = g_scratch + (size_t)b * CH * LEN;
    float* ob = out + (size_t)b * LEN * CH;
    const int lane = threadIdx.x & 31;
    const int wrp  = threadIdx.x >> 5;
#pragma unroll
    for (int m = 0; m < 4; m++) {
        int c = wrp * 4 + m;
#pragma unroll
        for (int k = 0; k < 4; k++) {
            int l = lane + k * 32;
            tile[l][c] = sb[(size_t)(c0 + c) * LEN + (l0 + l)];
        }
    }
    __syncthreads();
#pragma unroll
    for (int k = 0; k < 16; k++) {
        int l = wrp + k * 8;
        ob[(size_t)(l0 + l) * CH + (c0 + lane)] = tile[l][lane];
    }
}

// ------------------------------ launch -------------------------------------
extern "C" void kernel_launch(void* const* d_in, const int* in_sizes, int n_in,
                              void* d_out, int out_size) {
    const float* x = (const float*)d_in[0];
    float* out = (float*)d_out;

    twiddle_init_kernel<<<9, 256>>>();
    transpose_fwd_kernel<<<dim3(CH / 32, LEN / 128, BATCH), 256>>>(x);
    fourier_block_kernel<<<BATCH * CH, TPB>>>();
    transpose_bwd_kernel<<<dim3(CH / 32, LEN / 128, BATCH), 256>>>(out);
}